// round 10
// baseline (speedup 1.0000x reference)
#include <cuda_runtime.h>
#include <math.h>

#define MBLOCK 256
#define MGRID  912          // ~6 blocks/SM on 152 SMs; grid-stride handles any chip

#define TABN   512
#define TABSC  32.0f        // TABN / 16  (range [-8, 8])
#define TABLO  8.0f
#define TABW   16           // channels interleaved per node

// node-major interleaved table: g_tabi[k*16 + c], k = 0..TABN (inclusive halo)
__device__ float g_tabi[(TABN + 1) * TABW];

__device__ __forceinline__ float fast_tanh(float x) {
    float y;
    asm("tanh.approx.f32 %0, %1;" : "=f"(y) : "f"(x));
    return y;
}

// Full per-unit network. P layout: 0-2 W0, 3-5 B0, 6-8 T0, 9-17 W1, 18-20 B1,
// 21-23 T1, 24-32 W2, 33-35 B2, 36-38 T2, 39-41 W3, 42 B3, 43 T3
__device__ __forceinline__ float net_eval(float v, const float* __restrict__ P)
{
    float h[3], g[3];
#pragma unroll
    for (int i = 0; i < 3; i++) {
        float a = fmaf(P[0 + i], v, P[3 + i]);
        h[i] = fmaf(P[6 + i], fast_tanh(a), a);
    }
#pragma unroll
    for (int i = 0; i < 3; i++) {
        float a = P[18 + i];
        a = fmaf(P[9 + 3*i + 0], h[0], a);
        a = fmaf(P[9 + 3*i + 1], h[1], a);
        a = fmaf(P[9 + 3*i + 2], h[2], a);
        g[i] = fmaf(P[21 + i], fast_tanh(a), a);
    }
#pragma unroll
    for (int i = 0; i < 3; i++) {
        float a = P[33 + i];
        a = fmaf(P[24 + 3*i + 0], g[0], a);
        a = fmaf(P[24 + 3*i + 1], g[1], a);
        a = fmaf(P[24 + 3*i + 2], g[2], a);
        h[i] = fmaf(P[36 + i], fast_tanh(a), a);
    }
    float a = P[42];
    a = fmaf(P[39 + 0], h[0], a);
    a = fmaf(P[39 + 1], h[1], a);
    a = fmaf(P[39 + 2], h[2], a);
    return fmaf(P[43], fast_tanh(a), a);
}

__device__ __forceinline__ float lik_eval(float x, const float* __restrict__ P)
{
    float L = net_eval(x - 0.5f, P);
    float U = net_eval(x + 0.5f, P);
    // |sigmoid(U)-sigmoid(L)| = 0.5 |tanh(U/2)-tanh(L/2)| (precise tanhf here)
    float lik = 0.5f * fabsf(tanhf(0.5f * U) - tanhf(0.5f * L));
    return fmaxf(lik, 1e-9f);
}

// Build: each block stages ALL 16 channels' params in smem, then each thread
// evaluates one (node, channel) entry. (TABN+1)*16 = 8208 entries, 33 blocks.
__global__ void __launch_bounds__(256) eb_build(
    const float* __restrict__ m0, const float* __restrict__ b0, const float* __restrict__ f0,
    const float* __restrict__ m1, const float* __restrict__ b1, const float* __restrict__ f1,
    const float* __restrict__ m2, const float* __restrict__ b2, const float* __restrict__ f2,
    const float* __restrict__ m3, const float* __restrict__ b3, const float* __restrict__ f3)
{
    __shared__ float P[16 * 44];
    const int tid = threadIdx.x;

    for (int t = tid; t < 16 * 44; t += 256) {
        int c = t / 44, s = t % 44;
        float v;
        if      (s <  3) v = log1pf(expf(m0[c*3 + s]));
        else if (s <  6) v = b0[c*3 + (s-3)];
        else if (s <  9) v = tanhf(f0[c*3 + (s-6)]);
        else if (s < 18) v = log1pf(expf(m1[c*9 + (s-9)]));
        else if (s < 21) v = b1[c*3 + (s-18)];
        else if (s < 24) v = tanhf(f1[c*3 + (s-21)]);
        else if (s < 33) v = log1pf(expf(m2[c*9 + (s-24)]));
        else if (s < 36) v = b2[c*3 + (s-33)];
        else if (s < 39) v = tanhf(f2[c*3 + (s-36)]);
        else if (s < 42) v = log1pf(expf(m3[c*3 + (s-39)]));
        else if (s < 43) v = b3[c];
        else             v = tanhf(f3[c]);
        P[t] = v;
    }
    __syncthreads();

    int t = blockIdx.x * 256 + tid;
    if (t >= (TABN + 1) * TABW) return;
    const int c = t & 15;
    const int k = t >> 4;
    const float x = (float)k * (1.0f / TABSC) - TABLO;
    g_tabi[t] = lik_eval(x, P + c * 44);
}

// ---------------------------- main kernel -----------------------------------
__device__ __forceinline__ float lut_sm(const float* __restrict__ tab, float x, int c)
{
    float u = fmaf(x, TABSC, TABLO * TABSC);              // (x+8)*32
    u = fminf(fmaxf(u, 0.0f), (float)(TABN - 1) - 1e-3f);
    int   k = (int)u;
    float f = u - (float)k;
    float y0 = tab[k * TABW + c];
    float y1 = tab[k * TABW + TABW + c];
    return fmaf(f, y1 - y0, y0);
}

__device__ __forceinline__ float4 shift4(float4 a, float4 n)
{
    float4 x;
    x.x = a.x + n.x - 0.5f;
    x.y = a.y + n.y - 0.5f;
    x.z = a.z + n.z - 0.5f;
    x.w = a.w + n.w - 0.5f;
    return x;
}
__device__ __forceinline__ float4 lik4(const float* __restrict__ tab, float4 x, int c)
{
    float4 l;
    l.x = lut_sm(tab, x.x, c + 0);
    l.y = lut_sm(tab, x.y, c + 1);
    l.z = lut_sm(tab, x.z, c + 2);
    l.w = lut_sm(tab, x.w, c + 3);
    return l;
}

// Grid-stride streaming kernel; table lives in shared memory (no L1 gathers).
__global__ void __launch_bounds__(MBLOCK) eb_main(
    const float4* __restrict__ inp, const float4* __restrict__ noi,
    float4* __restrict__ outx, float4* __restrict__ outl, int total8)
{
    __shared__ float tab[(TABN + 1) * TABW];
    for (int i = threadIdx.x; i < (TABN + 1) * TABW; i += MBLOCK)
        tab[i] = g_tabi[i];
    __syncthreads();

    const int stride = MGRID * MBLOCK;
    for (int t = blockIdx.x * MBLOCK + threadIdx.x; t < total8; t += stride) {
        const int t2 = t + total8;

        float4 a0 = __ldcs(&inp[t]);
        float4 n0 = __ldcs(&noi[t]);
        float4 a1 = __ldcs(&inp[t2]);
        float4 n1 = __ldcs(&noi[t2]);

        float4 x0 = shift4(a0, n0);
        float4 x1 = shift4(a1, n1);
        __stcs(&outx[t],  x0);
        __stcs(&outx[t2], x1);

        const int c0 = (t  * 4) & 15;   // c in {0,4,8,12}
        const int c1 = (t2 * 4) & 15;
        __stcs(&outl[t],  lik4(tab, x0, c0));
        __stcs(&outl[t2], lik4(tab, x1, c1));
    }
}

// generic tail: elements [start, total) — gathers straight from gmem table
__global__ void eb_tail(const float* __restrict__ inp, const float* __restrict__ noi,
                        float* __restrict__ out, int start, int total)
{
    int i = start + blockIdx.x * blockDim.x + threadIdx.x;
    if (i >= total) return;
    float x = inp[i] + noi[i] - 0.5f;
    out[i] = x;
    float u = fmaf(x, TABSC, TABLO * TABSC);
    u = fminf(fmaxf(u, 0.0f), (float)(TABN - 1) - 1e-3f);
    int   k = (int)u;
    float f = u - (float)k;
    int   c = i & 15;
    float y0 = g_tabi[k * TABW + c];
    float y1 = g_tabi[k * TABW + TABW + c];
    out[total + i] = fmaf(f, y1 - y0, y0);
}

extern "C" void kernel_launch(void* const* d_in, const int* in_sizes, int n_in,
                              void* d_out, int out_size)
{
    const float* inp = (const float*)d_in[0];
    const float* noi = (const float*)d_in[1];

    eb_build<<<((TABN + 1) * TABW + 255) / 256, 256>>>(
        (const float*)d_in[2],  (const float*)d_in[3],  (const float*)d_in[4],
        (const float*)d_in[5],  (const float*)d_in[6],  (const float*)d_in[7],
        (const float*)d_in[8],  (const float*)d_in[9],  (const float*)d_in[10],
        (const float*)d_in[11], (const float*)d_in[12], (const float*)d_in[13]);

    const int total  = in_sizes[0];    // N * C
    const int total8 = total / 8;      // pairs of float4
    float* out = (float*)d_out;

    if (total8 > 0) {
        int grid = (total8 + MBLOCK - 1) / MBLOCK;
        if (grid > MGRID) grid = MGRID;
        eb_main<<<grid, MBLOCK>>>(
            (const float4*)inp, (const float4*)noi,
            (float4*)out, (float4*)(out + total), total8);
    }
    if (total8 * 8 < total) {
        eb_tail<<<1, 64>>>(inp, noi, out, total8 * 8, total);
    }
}

// round 11
// speedup vs baseline: 1.2567x; 1.2567x over previous
#include <cuda_runtime.h>
#include <math.h>

#define MBLOCK 256

#define TABN   1024
#define TABSC  64.0f      // TABN / 16  (range [-8, 8])
#define TABLO  8.0f

// likelihood lookup: per channel, TABN nodes on [-8,8], entry k = (y_k, y_{k+1})
__device__ float2 g_tab[16 * TABN];

__device__ __forceinline__ float fast_tanh(float x) {
    float y;
    asm("tanh.approx.f32 %0, %1;" : "=f"(y) : "f"(x));
    return y;
}

// Full per-unit network. P: 0-2 W0, 3-5 B0, 6-8 T0, 9-17 W1, 18-20 B1, 21-23 T1,
// 24-32 W2, 33-35 B2, 36-38 T2, 39-41 W3, 42 B3, 43 T3
__device__ __forceinline__ float net_eval(float v, const float* __restrict__ P)
{
    float h[3], g[3];
#pragma unroll
    for (int i = 0; i < 3; i++) {
        float a = fmaf(P[0 + i], v, P[3 + i]);
        h[i] = fmaf(P[6 + i], fast_tanh(a), a);
    }
#pragma unroll
    for (int i = 0; i < 3; i++) {
        float a = P[18 + i];
        a = fmaf(P[9 + 3*i + 0], h[0], a);
        a = fmaf(P[9 + 3*i + 1], h[1], a);
        a = fmaf(P[9 + 3*i + 2], h[2], a);
        g[i] = fmaf(P[21 + i], fast_tanh(a), a);
    }
#pragma unroll
    for (int i = 0; i < 3; i++) {
        float a = P[33 + i];
        a = fmaf(P[24 + 3*i + 0], g[0], a);
        a = fmaf(P[24 + 3*i + 1], g[1], a);
        a = fmaf(P[24 + 3*i + 2], g[2], a);
        h[i] = fmaf(P[36 + i], fast_tanh(a), a);
    }
    float a = P[42];
    a = fmaf(P[39 + 0], h[0], a);
    a = fmaf(P[39 + 1], h[1], a);
    a = fmaf(P[39 + 2], h[2], a);
    return fmaf(P[43], fast_tanh(a), a);
}

__device__ __forceinline__ float lik_eval(float x, const float* __restrict__ P)
{
    float L = net_eval(x - 0.5f, P);
    float U = net_eval(x + 0.5f, P);
    float lik = 0.5f * fabsf(tanhf(0.5f * U) - tanhf(0.5f * L));
    return fmaxf(lik, 1e-9f);
}

// 64 blocks: block b -> channel b/4, nodes [(b%4)*256, +256). One eval/thread.
__global__ void __launch_bounds__(256) eb_build(
    const float* __restrict__ m0, const float* __restrict__ b0, const float* __restrict__ f0,
    const float* __restrict__ m1, const float* __restrict__ b1, const float* __restrict__ f1,
    const float* __restrict__ m2, const float* __restrict__ b2, const float* __restrict__ f2,
    const float* __restrict__ m3, const float* __restrict__ b3, const float* __restrict__ f3)
{
    __shared__ float P[44];
    __shared__ float Y[257];
    const int c    = blockIdx.x >> 2;
    const int base = (blockIdx.x & 3) << 8;
    const int tid  = threadIdx.x;

    if (tid < 44) {
        int s = tid;
        float v;
        if      (s <  3) v = log1pf(expf(m0[c*3 + s]));
        else if (s <  6) v = b0[c*3 + (s-3)];
        else if (s <  9) v = tanhf(f0[c*3 + (s-6)]);
        else if (s < 18) v = log1pf(expf(m1[c*9 + (s-9)]));
        else if (s < 21) v = b1[c*3 + (s-18)];
        else if (s < 24) v = tanhf(f1[c*3 + (s-21)]);
        else if (s < 33) v = log1pf(expf(m2[c*9 + (s-24)]));
        else if (s < 36) v = b2[c*3 + (s-33)];
        else if (s < 39) v = tanhf(f2[c*3 + (s-36)]);
        else if (s < 42) v = log1pf(expf(m3[c*3 + (s-39)]));
        else if (s < 43) v = b3[c];
        else             v = tanhf(f3[c]);
        P[s] = v;
    }
    __syncthreads();

    {
        int k = base + tid;
        Y[tid] = lik_eval((float)k * (1.0f / TABSC) - TABLO, P);
        if (tid == 0)
            Y[256] = lik_eval((float)(base + 256) * (1.0f / TABSC) - TABLO, P);
    }
    __syncthreads();

    g_tab[(c << 10) + base + tid] = make_float2(Y[tid], Y[tid + 1]);
}

// ---------------------------- main kernel -----------------------------------
__device__ __forceinline__ float lut(float x, int c)
{
    float u = fmaf(x, TABSC, TABLO * TABSC);              // (x+8)*64
    u = fminf(fmaxf(u, 0.0f), (float)(TABN - 2) + 0.999f);
    int   k = (int)u;
    float f = u - (float)k;
    float2 p = __ldg(&g_tab[(c << 10) + k]);
    return fmaf(f, p.y - p.x, p.x);
}

__device__ __forceinline__ float4 shift4(float4 a, float4 n)
{
    float4 x;
    x.x = a.x + n.x - 0.5f;
    x.y = a.y + n.y - 0.5f;
    x.z = a.z + n.z - 0.5f;
    x.w = a.w + n.w - 0.5f;
    return x;
}
__device__ __forceinline__ float4 lik4(float4 x, int c)
{
    float4 l;
    l.x = lut(x.x, c + 0);
    l.y = lut(x.y, c + 1);
    l.z = lut(x.z, c + 2);
    l.w = lut(x.w, c + 3);
    return l;
}

// PDL: streaming phase needs no table; grid-dependency sync only before gathers.
__global__ void __launch_bounds__(MBLOCK) eb_main(
    const float4* __restrict__ inp, const float4* __restrict__ noi,
    float4* __restrict__ outx, float4* __restrict__ outl, int total8)
{
    int t = blockIdx.x * MBLOCK + threadIdx.x;
    if (t >= total8) {
#if __CUDA_ARCH__ >= 900
        cudaGridDependencySynchronize();
#endif
        return;
    }
    const int t2 = t + total8;

    float4 a0 = __ldcs(&inp[t]);
    float4 n0 = __ldcs(&noi[t]);
    float4 a1 = __ldcs(&inp[t2]);
    float4 n1 = __ldcs(&noi[t2]);

    float4 x0 = shift4(a0, n0);
    float4 x1 = shift4(a1, n1);
    __stcs(&outx[t],  x0);
    __stcs(&outx[t2], x1);

#if __CUDA_ARCH__ >= 900
    cudaGridDependencySynchronize();   // eb_build's table now visible
#endif

    const int c0 = (t  * 4) & 15;   // c in {0,4,8,12}
    const int c1 = (t2 * 4) & 15;
    __stcs(&outl[t],  lik4(x0, c0));
    __stcs(&outl[t2], lik4(x1, c1));
}

// generic tail: elements [start, total)
__global__ void eb_tail(const float* __restrict__ inp, const float* __restrict__ noi,
                        float* __restrict__ out, int start, int total)
{
    int i = start + blockIdx.x * blockDim.x + threadIdx.x;
    if (i >= total) return;
    float x = inp[i] + noi[i] - 0.5f;
    out[i] = x;
    out[total + i] = lut(x, i & 15);
}

extern "C" void kernel_launch(void* const* d_in, const int* in_sizes, int n_in,
                              void* d_out, int out_size)
{
    const float* inp = (const float*)d_in[0];
    const float* noi = (const float*)d_in[1];

    eb_build<<<64, 256>>>((const float*)d_in[2],  (const float*)d_in[3],  (const float*)d_in[4],
                          (const float*)d_in[5],  (const float*)d_in[6],  (const float*)d_in[7],
                          (const float*)d_in[8],  (const float*)d_in[9],  (const float*)d_in[10],
                          (const float*)d_in[11], (const float*)d_in[12], (const float*)d_in[13]);

    const int total  = in_sizes[0];    // N * C
    const int total8 = total / 8;      // pairs of float4
    float* out = (float*)d_out;

    if (total8 > 0) {
        cudaLaunchConfig_t cfg = {};
        cfg.gridDim  = dim3((total8 + MBLOCK - 1) / MBLOCK, 1, 1);
        cfg.blockDim = dim3(MBLOCK, 1, 1);
        cudaLaunchAttribute attr[1];
        attr[0].id = cudaLaunchAttributeProgrammaticStreamSerialization;
        attr[0].val.programmaticStreamSerializationAllowed = 1;
        cfg.attrs = attr;
        cfg.numAttrs = 1;
        cudaLaunchKernelEx(&cfg, eb_main,
                           (const float4*)inp, (const float4*)noi,
                           (float4*)out, (float4*)(out + total), total8);
    }
    if (total8 * 8 < total) {
        eb_tail<<<1, 64>>>(inp, noi, out, total8 * 8, total);
    }
}